// round 16
// baseline (speedup 1.0000x reference)
#include <cuda_runtime.h>
#include <cuda_fp16.h>
#include <math.h>
#include <cstdint>

// ---------------------------------------------------------------------------
// Problem constants:  x[B=4,S=4,L=1024,F=256]; D=256, H=8, DH=32; N = B*S = 16
// ---------------------------------------------------------------------------
#define NSEQ 16
#define LSEQ 1024
#define DDIM 256
#define NHEAD 8
#define MROWS (NSEQ * LSEQ)   // 16384

// fp16 planes.  Q/K/V/A single (hi) plane.  Wq/Wk hi only (1-term QK);
// Wv/Wo keep hi+lo (direct output path).
__device__ __half g_Xh[MROWS * DDIM];
__device__ __half g_Qh[MROWS * DDIM];
__device__ __half g_Kh[MROWS * DDIM];
__device__ __half g_Vh[MROWS * DDIM];
__device__ __half g_Ah[MROWS * DDIM];
__device__ __half g_Wqh[DDIM * DDIM];
__device__ __half g_Wkh[DDIM * DDIM];
__device__ __half g_Wvh[DDIM * DDIM], g_Wvl[DDIM * DDIM];
__device__ __half g_Woh[DDIM * DDIM], g_Wol[DDIM * DDIM];
__device__ float  g_O[MROWS * DDIM];

// ===========================================================================
// helpers
// ===========================================================================
__device__ __forceinline__ uint32_t smem_u32(const void* p) {
    uint32_t a;
    asm("{ .reg .u64 t; cvta.to.shared.u64 t, %1; cvt.u32.u64 %0, t; }"
        : "=r"(a) : "l"(p));
    return a;
}
__device__ __forceinline__ void ldmx4(uint32_t (&r)[4], uint32_t addr) {
    asm volatile("ldmatrix.sync.aligned.m8n8.x4.shared.b16 {%0,%1,%2,%3}, [%4];"
                 : "=r"(r[0]), "=r"(r[1]), "=r"(r[2]), "=r"(r[3]) : "r"(addr));
}
__device__ __forceinline__ void ldmx4t(uint32_t (&r)[4], uint32_t addr) {
    asm volatile("ldmatrix.sync.aligned.m8n8.x4.trans.shared.b16 {%0,%1,%2,%3}, [%4];"
                 : "=r"(r[0]), "=r"(r[1]), "=r"(r[2]), "=r"(r[3]) : "r"(addr));
}
__device__ __forceinline__ void mma16816(float (&c)[4], const uint32_t (&a)[4],
                                         const uint32_t (&b)[2]) {
    asm volatile(
        "mma.sync.aligned.m16n8k16.row.col.f32.f16.f16.f32 "
        "{%0,%1,%2,%3}, {%4,%5,%6,%7}, {%8,%9}, {%0,%1,%2,%3};"
        : "+f"(c[0]), "+f"(c[1]), "+f"(c[2]), "+f"(c[3])
        : "r"(a[0]), "r"(a[1]), "r"(a[2]), "r"(a[3]), "r"(b[0]), "r"(b[1]));
}
__device__ __forceinline__ uint32_t packf16(float x0, float x1) {
    uint32_t r;
    asm("cvt.rn.f16x2.f32 %0, %1, %2;" : "=r"(r) : "f"(x1), "f"(x0));
    return r;
}
__device__ __forceinline__ uint32_t h2exp2i(uint32_t x) {
    uint32_t r;
    asm("ex2.approx.f16x2 %0, %1;" : "=r"(r) : "r"(x));
    return r;
}
__device__ __forceinline__ uint32_t hadd2i(uint32_t a, uint32_t b) {
    uint32_t r;
    asm("add.f16x2 %0, %1, %2;" : "=r"(r) : "r"(a), "r"(b));
    return r;
}
__device__ __forceinline__ void cp16(uint32_t dst, const void* src) {
    asm volatile("cp.async.cg.shared.global [%0], [%1], 16;"
                 :: "r"(dst), "l"(src) : "memory");
}
#define CP_COMMIT() asm volatile("cp.async.commit_group;" ::: "memory")
#define CP_WAIT(n)  asm volatile("cp.async.wait_group %0;" :: "n"(n) : "memory")

// XOR chunk swizzle for 32-half (64B) rows: conflict-free fills + ldmatrix
__device__ __forceinline__ int swz(int r, int c) {   // half offset in tile
    return r * 32 + ((c ^ ((r >> 1) & 3)) << 3);
}

// ===========================================================================
// fused prep: x -> Xh (blocks 0..16383); weights (blocks 16384..17407):
//   z=0: Wq -> hi; z=1: Wk -> hi; z=2: Wv -> hi+lo; z=3: Wo -> hi+lo.
// ===========================================================================
__global__ __launch_bounds__(256) void prep_kernel(
    const float* __restrict__ x,
    const float* __restrict__ Wq, const float* __restrict__ Wk,
    const float* __restrict__ Wv, const float* __restrict__ Wo,
    __half* __restrict__ Xh,
    __half* __restrict__ Wqh, __half* __restrict__ Wkh,
    __half* __restrict__ Wvh, __half* __restrict__ Wvl,
    __half* __restrict__ Woh, __half* __restrict__ Wol)
{
    const int b = blockIdx.x;
    if (b < 16384) {
        int i = b * 256 + threadIdx.x;
        Xh[i] = __float2half_rn(x[i]);
    } else {
        int zb = b - 16384;
        int z  = zb >> 8;
        int i  = (zb & 255) * 256 + threadIdx.x;
        if (z == 0) {
            Wqh[i] = __float2half_rn(Wq[i]);
        } else if (z == 1) {
            Wkh[i] = __float2half_rn(Wk[i]);
        } else if (z == 2) {
            float v = Wv[i];
            __half h = __float2half_rn(v);
            Wvh[i] = h;
            Wvl[i] = __float2half_rn(v - __half2float(h));
        } else {
            float v = Wo[i];
            __half h = __float2half_rn(v);
            Woh[i] = h;
            Wol[i] = __float2half_rn(v - __half2float(h));
        }
    }
}

// ===========================================================================
// Persistent weights-resident GEMM: CTA = 64n column stripe; W tile loaded
// ONCE; CTA iterates over `nblocks` 128-row M-blocks with A (hi plane only)
// streamed in a continuously double-buffered 32-col chunk pipeline.
// 8 warps (4m x 2n).  nterms: 1 -> Ah*Wh;  2 -> Ah*(Wh+Wl).
// outmode: 0=f32, 2=hi.
// smem: WH 0..32K, WL 32..64K, X stage s at 64K + (s&1)*8K.  Total 80K.
// RACE FIX (R16): trailing __syncthreads() per stage — all warps must finish
// reading buffer (gs&1) before the next iteration's prefetch overwrites it.
// ===========================================================================
#define GEMM_SMEM 81920

__device__ __forceinline__ void gemm_body64(
    const __half* __restrict__ Aph,
    const __half* __restrict__ Wph, const __half* __restrict__ Wpl,
    const float* __restrict__ bias, float outscale, int outmode, int nterms,
    int nblocks,
    __half* __restrict__ Ch, float* __restrict__ Cf,
    int bm0, int bn, uint32_t sb)
{
    const int tid  = threadIdx.x;
    const int lane = tid & 31;
    const int wid  = tid >> 5;
    const int wm   = wid & 3;
    const int wn   = wid >> 2;
    const int qd   = lane >> 3;

    const uint32_t WH = sb;
    const uint32_t WL = sb + 32768;
    const uint32_t X0 = sb + 65536;

    // ---- prologue: W planes (one-time) + A stage 0
    #pragma unroll
    for (int i = 0; i < 8; i++) {
        int s = tid + i * 256;            // 0..2047
        int r = s >> 5, cc = s & 31;      // row 0..63, col-chunk 0..31
        int kc = cc >> 2, c = cc & 3;
        uint32_t d = (uint32_t)(kc * 2048 + swz(r, c)) * 2;
        size_t src = (size_t)(bn + r) * 256 + cc * 8;
        cp16(WH + d, &Wph[src]);
        if (nterms >= 2) cp16(WL + d, &Wpl[src]);
    }
    #pragma unroll
    for (int i = 0; i < 2; i++) {
        int s = tid + i * 256;
        int r = s >> 2, c = s & 3;
        uint32_t d = (uint32_t)swz(r, c) * 2;
        size_t src = (size_t)(bm0 + r) * 256 + c * 8;
        cp16(X0 + d, &Aph[src]);
    }
    CP_COMMIT();

    const int a_row = wm * 32 + (lane & 15);
    const int b_row = wn * 32 + (qd & 1) * 8 + (lane & 7);
    const int nstages = nblocks * 8;

    #pragma unroll 1
    for (int it = 0; it < nblocks; it++) {
        const int bm = bm0 + it * 128;

        float acc[2][4][4];
        #pragma unroll
        for (int i = 0; i < 2; i++)
            #pragma unroll
            for (int j = 0; j < 4; j++)
                #pragma unroll
                for (int k = 0; k < 4; k++) acc[i][j][k] = 0.f;

        #pragma unroll 1
        for (int kc = 0; kc < 8; kc++) {
            const int gs = it * 8 + kc;
            const int st = gs & 1;
            if (gs + 1 < nstages) {
                const int ngs = gs + 1;
                const int nbm = bm0 + (ngs >> 3) * 128;
                const int nk0 = (ngs & 7) * 32;
                uint32_t xh = X0 + (ngs & 1) * 8192;
                #pragma unroll
                for (int i = 0; i < 2; i++) {
                    int s = tid + i * 256;
                    int r = s >> 2, c = s & 3;
                    uint32_t d = (uint32_t)swz(r, c) * 2;
                    size_t src = (size_t)(nbm + r) * 256 + nk0 + c * 8;
                    cp16(xh + d, &Aph[src]);
                }
                CP_COMMIT();
                CP_WAIT(1);
            } else {
                CP_WAIT(0);
            }
            __syncthreads();

            const uint32_t xh = X0 + st * 8192;
            const uint32_t wkc = (uint32_t)(kc * 2048) * 2;

            #pragma unroll
            for (int ks = 0; ks < 32; ks += 16) {
                uint32_t ah[2][4];
                #pragma unroll
                for (int mt = 0; mt < 2; mt++) {
                    int row = a_row + mt * 16;
                    int c   = (lane >> 4) + (ks >> 3);
                    uint32_t off = (uint32_t)swz(row, c) * 2;
                    ldmx4(ah[mt], xh + off);
                }
                uint32_t bh[4][2], bl[4][2];
                #pragma unroll
                for (int j = 0; j < 2; j++) {
                    int row = b_row + 16 * j;
                    int c   = (qd >> 1) + (ks >> 3);
                    uint32_t off = (uint32_t)swz(row, c) * 2;
                    uint32_t r4[4];
                    ldmx4(r4, WH + wkc + off);
                    bh[2*j][0] = r4[0]; bh[2*j+1][0] = r4[1];
                    bh[2*j][1] = r4[2]; bh[2*j+1][1] = r4[3];
                    if (nterms >= 2) {
                        ldmx4(r4, WL + wkc + off);
                        bl[2*j][0] = r4[0]; bl[2*j+1][0] = r4[1];
                        bl[2*j][1] = r4[2]; bl[2*j+1][1] = r4[3];
                    }
                }
                #pragma unroll
                for (int mt = 0; mt < 2; mt++)
                    #pragma unroll
                    for (int nt = 0; nt < 4; nt++) {
                        mma16816(acc[mt][nt], ah[mt], bh[nt]);
                        if (nterms >= 2) mma16816(acc[mt][nt], ah[mt], bl[nt]);
                    }
            }
            // RACE FIX: all warps must be done reading this stage's X buffer
            // before the next iteration's cp.async overwrites it.
            __syncthreads();
        }

        // ---- epilogue for this block (regs + gmem only; no smem)
        #pragma unroll
        for (int mt = 0; mt < 2; mt++) {
            #pragma unroll
            for (int nt = 0; nt < 4; nt++) {
                int r0 = bm + wm * 32 + mt * 16 + (lane >> 2);
                int c  = bn + wn * 32 + nt * 8 + (lane & 3) * 2;
                float b0 = bias[c], b1 = bias[c + 1];
                float v00 = (acc[mt][nt][0] + b0) * outscale;
                float v01 = (acc[mt][nt][1] + b1) * outscale;
                float v10 = (acc[mt][nt][2] + b0) * outscale;
                float v11 = (acc[mt][nt][3] + b1) * outscale;
                if (outmode == 2) {
                    *reinterpret_cast<uint32_t*>(&Ch[(size_t)r0 * 256 + c]) =
                        packf16(v00, v01);
                    *reinterpret_cast<uint32_t*>(&Ch[(size_t)(r0 + 8) * 256 + c]) =
                        packf16(v10, v11);
                } else {
                    *reinterpret_cast<float2*>(&Cf[(size_t)r0 * 256 + c]) =
                        make_float2(v00, v01);
                    *reinterpret_cast<float2*>(&Cf[(size_t)(r0 + 8) * 256 + c]) =
                        make_float2(v10, v11);
                }
            }
        }
    }
}

// fused QKV projection: grid (4, 16, 3); 8 M-blocks per CTA (single wave).
// Q/K: 1-term.  V: 2-term (direct output path).
__global__ __launch_bounds__(256, 2) void gemm_qkv(
    const __half* __restrict__ Xh,
    const __half* __restrict__ Wqh, const __half* __restrict__ Wkh,
    const __half* __restrict__ Wvh, const __half* __restrict__ Wvl,
    const float* __restrict__ bq, const float* __restrict__ bk,
    const float* __restrict__ bv,
    __half* __restrict__ Qh, __half* __restrict__ Kh, __half* __restrict__ Vh,
    float qscale)
{
    extern __shared__ __align__(16) char gsm[];
    const int z = blockIdx.z;
    const __half* Wph = (z == 0) ? Wqh : (z == 1) ? Wkh : Wvh;
    const __half* Wpl = (z == 2) ? Wvl : nullptr;
    const float* bias = (z == 0) ? bq : (z == 1) ? bk : bv;
    __half* Ch = (z == 0) ? Qh : (z == 1) ? Kh : Vh;
    const float sc = (z == 0) ? qscale : 1.f;
    const int nterms = (z == 2) ? 2 : 1;

    gemm_body64(Xh, Wph, Wpl, bias, sc, 2, nterms, 8,
                Ch, nullptr,
                blockIdx.y * 1024, blockIdx.x * 64, smem_u32(gsm));
}

// O projection (f32 out), grid (4, 64); 2 M-blocks per CTA; 2-term.
__global__ __launch_bounds__(256, 2) void gemm_o(
    const __half* __restrict__ Aph,
    const __half* __restrict__ Wph, const __half* __restrict__ Wpl,
    const float* __restrict__ bias, float* __restrict__ Cf)
{
    extern __shared__ __align__(16) char gsm[];
    gemm_body64(Aph, Wph, Wpl, bias, 1.f, 0, 2, 2, nullptr, Cf,
                blockIdx.y * 256, blockIdx.x * 64, smem_u32(gsm));
}

// ===========================================================================
// Flash attention via mma.sync (16 q-rows/warp, occ 3), 128-key smem tiles
// (2x64-key sub-rounds), cp.async double buffering.
// FIXED-BIAS softmax p = exp2(s - 8) in f16x2; HADD2 row sums.
// QK^T = qh*kh.  PV: P,V single fp16.
// ===========================================================================
#define TILE_HALFS (128 * 32)
#define TILE_BYTES (TILE_HALFS * 2)   // 8192
#define SM_BIAS 8.0f

__global__ __launch_bounds__(256, 3) void attn_mma(
    const __half* __restrict__ Qh,
    const __half* __restrict__ Kh, const __half* __restrict__ Vh,
    __half* __restrict__ Aoh)
{
    __shared__ __align__(16) __half Ksh[2][TILE_HALFS];
    __shared__ __align__(16) __half Vsh[2][TILE_HALFS];

    const int tid  = threadIdx.x;
    const int lane = tid & 31;
    const int w    = tid >> 5;                  // 0..7
    const int qd   = lane >> 3;
    const int n    = blockIdx.z;
    const int h    = blockIdx.y;
    const int qbase = blockIdx.x * 128 + w * 16;
    const size_t seqoff = (size_t)n * LSEQ * 256 + h * 32;

    const uint32_t kh0 = smem_u32(&Ksh[0][0]);
    const uint32_t vh0 = smem_u32(&Vsh[0][0]);

    // prologue: prefetch tile 0 (128 keys) into buffer 0
    #pragma unroll
    for (int i = 0; i < 2; i++) {
        int s = tid + i * 256;
        int r = s >> 2, c = s & 3;
        uint32_t d = (uint32_t)swz(r, c) * 2;
        size_t src = seqoff + (size_t)r * 256 + c * 8;
        cp16(kh0 + d, &Kh[src]);
        cp16(vh0 + d, &Vh[src]);
    }
    CP_COMMIT();

    // Q fragments (overlap with prefetch)
    uint32_t qh[2][4];
    #pragma unroll
    for (int kt = 0; kt < 2; kt++)
        #pragma unroll
        for (int pi = 0; pi < 4; pi++) {
            int row = qbase + (lane >> 2) + ((pi & 1) ? 8 : 0);
            int col = kt * 16 + (lane & 3) * 2 + ((pi & 2) ? 8 : 0);
            qh[kt][pi] = *reinterpret_cast<const uint32_t*>(
                &Qh[seqoff + (size_t)row * 256 + col]);
        }

    float out[4][4];
    #pragma unroll
    for (int j = 0; j < 4; j++)
        #pragma unroll
        for (int k = 0; k < 4; k++) out[j][k] = 0.f;
    float lpart[2] = {0.f, 0.f};

    const int kb_rowc = (qd & 1) * 8 + (lane & 7);

    #pragma unroll 1
    for (int t = 0; t < 8; t++) {
        const int buf = t & 1;
        if (t + 1 < 8) {
            const uint32_t bo = (buf ^ 1) * TILE_BYTES;
            #pragma unroll
            for (int i = 0; i < 2; i++) {
                int s = tid + i * 256;
                int r = s >> 2, c = s & 3;
                uint32_t d = (uint32_t)swz(r, c) * 2;
                size_t src = seqoff + (size_t)((t + 1) * 128 + r) * 256 + c * 8;
                cp16(kh0 + bo + d, &Kh[src]);
                cp16(vh0 + bo + d, &Vh[src]);
            }
            CP_COMMIT();
            CP_WAIT(1);
        } else {
            CP_WAIT(0);
        }
        __syncthreads();

        const uint32_t khB = kh0 + buf * TILE_BYTES;
        const uint32_t vhB = vh0 + buf * TILE_BYTES;

        #pragma unroll
        for (int s64 = 0; s64 < 2; s64++) {
            const int rbase = s64 * 64;

            // ---- scores S[16 q, 64 k], accumulator pre-biased to -8
            float sc[8][4];
            #pragma unroll
            for (int j = 0; j < 8; j++)
                #pragma unroll
                for (int k = 0; k < 4; k++) sc[j][k] = -SM_BIAS;

            #pragma unroll
            for (int kt = 0; kt < 2; kt++) {
                uint32_t bh[8][2];
                #pragma unroll
                for (int j = 0; j < 4; j++) {
                    int row = rbase + kb_rowc + 16 * j;
                    int c   = kt * 2 + (qd >> 1);
                    uint32_t off = (uint32_t)swz(row, c) * 2;
                    uint32_t r4[4];
                    ldmx4(r4, khB + off);
                    bh[2*j][0] = r4[0]; bh[2*j+1][0] = r4[1];
                    bh[2*j][1] = r4[2]; bh[2*j+1][1] = r4[3];
                }
                #pragma unroll
                for (int nt = 0; nt < 8; nt++)
                    mma16816(sc[nt], qh[kt], bh[nt]);
            }

            // ---- pack + f16x2 exp2 (outputs ARE the PV fragments)
            uint32_t p16[8][2];
            #pragma unroll
            for (int nt = 0; nt < 8; nt++) {
                p16[nt][0] = h2exp2i(packf16(sc[nt][0], sc[nt][1]));
                p16[nt][1] = h2exp2i(packf16(sc[nt][2], sc[nt][3]));
            }

            // ---- row-sum trees (HADD2), accumulate lsum in f32
            #pragma unroll
            for (int s = 0; s < 2; s++) {
                uint32_t t01 = hadd2i(p16[0][s], p16[1][s]);
                uint32_t t23 = hadd2i(p16[2][s], p16[3][s]);
                uint32_t t45 = hadd2i(p16[4][s], p16[5][s]);
                uint32_t t67 = hadd2i(p16[6][s], p16[7][s]);
                uint32_t tt  = hadd2i(hadd2i(t01, t23), hadd2i(t45, t67));
                __half2 hh = *reinterpret_cast<__half2*>(&tt);
                float2 ff = __half22float2(hh);
                lpart[s] += ff.x + ff.y;
            }

            // ---- PV: out += P @ V
            #pragma unroll
            for (int ktpv = 0; ktpv < 4; ktpv++) {
                uint32_t pah[4];
                pah[0] = p16[2 * ktpv][0];
                pah[1] = p16[2 * ktpv][1];
                pah[2] = p16[2 * ktpv + 1][0];
                pah[3] = p16[2 * ktpv + 1][1];

                uint32_t vh[4][2];
                #pragma unroll
                for (int j = 0; j < 2; j++) {
                    int row = rbase + ktpv * 16 + kb_rowc;
                    int c   = 2 * j + (qd >> 1);
                    uint32_t off = (uint32_t)swz(row, c) * 2;
                    uint32_t r4[4];
                    ldmx4t(r4, vhB + off);
                    vh[2*j][0] = r4[0];   vh[2*j][1] = r4[1];
                    vh[2*j+1][0] = r4[2]; vh[2*j+1][1] = r4[3];
                }
                #pragma unroll
                for (int ntd = 0; ntd < 4; ntd++)
                    mma16816(out[ntd], pah, vh[ntd]);
            }
        }
        __syncthreads();
    }

    // ---- finalize
    float inv[2];
    #pragma unroll
    for (int s = 0; s < 2; s++) {
        float ls = lpart[s];
        ls += __shfl_xor_sync(0xffffffffu, ls, 1);
        ls += __shfl_xor_sync(0xffffffffu, ls, 2);
        inv[s] = 1.f / ls;
    }
    #pragma unroll
    for (int ntd = 0; ntd < 4; ntd++) {
        int r0 = qbase + (lane >> 2);
        int c  = h * 32 + ntd * 8 + (lane & 3) * 2;
        size_t base = (size_t)n * LSEQ * 256;
        float v00 = out[ntd][0] * inv[0];
        float v01 = out[ntd][1] * inv[0];
        float v10 = out[ntd][2] * inv[1];
        float v11 = out[ntd][3] * inv[1];
        *reinterpret_cast<uint32_t*>(&Aoh[base + (size_t)r0 * 256 + c]) =
            packf16(v00, v01);
        *reinterpret_cast<uint32_t*>(&Aoh[base + (size_t)(r0 + 8) * 256 + c]) =
            packf16(v10, v11);
    }
}

// ---------------------------------------------------------------------------
// Softmax pooling over L per (n, d)
// ---------------------------------------------------------------------------
__global__ __launch_bounds__(256) void pool_kernel(
    const float* __restrict__ O, float* __restrict__ out)
{
    const int n  = blockIdx.y;
    const int d0 = blockIdx.x * 32;
    const int dc = threadIdx.x & 31;
    const int g  = threadIdx.x >> 5;
    const int d  = d0 + dc;

    float m = -INFINITY, se = 0.f, sex = 0.f;
    for (int l = g; l < LSEQ; l += 8) {
        float x = O[((size_t)n * LSEQ + l) * DDIM + d];
        if (x > m) {
            float c = __expf(m - x);
            se *= c; sex *= c; m = x;
        }
        float p = __expf(x - m);
        se += p; sex += p * x;
    }

    __shared__ float sm[8][32], sse[8][32], ssex[8][32];
    sm[g][dc] = m; sse[g][dc] = se; ssex[g][dc] = sex;
    __syncthreads();

    if (g == 0) {
        #pragma unroll
        for (int o = 1; o < 8; o++) {
            float m2 = sm[o][dc], se2 = sse[o][dc], sex2 = ssex[o][dc];
            if (m2 > m) {
                float c = __expf(m - m2);
                se *= c; sex *= c; m = m2;
            }
            float c2 = __expf(m2 - m);
            se += se2 * c2; sex += sex2 * c2;
        }
        out[(size_t)n * DDIM + d] = sex / se;
    }
}

// ---------------------------------------------------------------------------
// Launch
// ---------------------------------------------------------------------------
extern "C" void kernel_launch(void* const* d_in, const int* in_sizes, int n_in,
                              void* d_out, int out_size)
{
    const float* x  = (const float*)d_in[0];
    const float* Wq = (const float*)d_in[1];
    const float* bq = (const float*)d_in[2];
    const float* Wk = (const float*)d_in[3];
    const float* bk = (const float*)d_in[4];
    const float* Wv = (const float*)d_in[5];
    const float* bv = (const float*)d_in[6];
    const float* Wo = (const float*)d_in[7];
    const float* bo = (const float*)d_in[8];
    float* out = (float*)d_out;

    __half *Xh, *Qh, *Kh, *Vh, *Ah;
    __half *Wqh, *Wkh, *Wvh, *Wvl, *Woh, *Wol;
    float* O;
    cudaGetSymbolAddress((void**)&Xh, g_Xh);
    cudaGetSymbolAddress((void**)&Qh, g_Qh);
    cudaGetSymbolAddress((void**)&Kh, g_Kh);
    cudaGetSymbolAddress((void**)&Vh, g_Vh);
    cudaGetSymbolAddress((void**)&Ah, g_Ah);
    cudaGetSymbolAddress((void**)&Wqh, g_Wqh);
    cudaGetSymbolAddress((void**)&Wkh, g_Wkh);
    cudaGetSymbolAddress((void**)&Wvh, g_Wvh); cudaGetSymbolAddress((void**)&Wvl, g_Wvl);
    cudaGetSymbolAddress((void**)&Woh, g_Woh); cudaGetSymbolAddress((void**)&Wol, g_Wol);
    cudaGetSymbolAddress((void**)&O, g_O);

    cudaFuncSetAttribute(gemm_qkv, cudaFuncAttributeMaxDynamicSharedMemorySize,
                         GEMM_SMEM);
    cudaFuncSetAttribute(gemm_o, cudaFuncAttributeMaxDynamicSharedMemorySize,
                         GEMM_SMEM);

    // exp2-domain scale: (1/sqrt(DH)) * log2(e)
    const float qscale = 0.17677669529663687f * 1.4426950408889634f;

    prep_kernel<<<16384 + 4 * 256, 256>>>(x, Wq, Wk, Wv, Wo,
                                          Xh, Wqh, Wkh, Wvh, Wvl, Woh, Wol);

    dim3 qkvGrid(4, 16, 3);     // 8 M-blocks per CTA; single wave at occ 2
    gemm_qkv<<<qkvGrid, 256, GEMM_SMEM>>>(Xh, Wqh, Wkh, Wvh, Wvl,
                                          bq, bk, bv, Qh, Kh, Vh, qscale);

    dim3 aGrid(LSEQ / 128, NHEAD, NSEQ);   // (8, 8, 16) = 1024 CTAs
    attn_mma<<<aGrid, 256>>>(Qh, Kh, Vh, Ah);

    dim3 oGrid(4, 64);          // 2 M-blocks per CTA
    gemm_o<<<oGrid, 256, GEMM_SMEM>>>(Ah, Woh, Wol, bo, O);

    dim3 pGrid(DDIM / 32, NSEQ);
    pool_kernel<<<pGrid, 256>>>(O, out);
}

// round 17
// speedup vs baseline: 1.1254x; 1.1254x over previous
#include <cuda_runtime.h>
#include <cuda_fp16.h>
#include <math.h>
#include <cstdint>

// ---------------------------------------------------------------------------
// Problem constants:  x[B=4,S=4,L=1024,F=256]; D=256, H=8, DH=32; N = B*S = 16
// ---------------------------------------------------------------------------
#define NSEQ 16
#define LSEQ 1024
#define DDIM 256
#define NHEAD 8
#define MROWS (NSEQ * LSEQ)   // 16384

// fp16 planes.  Q/K/V/A single (hi) plane.  Wq/Wk hi only (1-term QK);
// Wv/Wo keep hi+lo (direct output path).
__device__ __half g_Xh[MROWS * DDIM];
__device__ __half g_Qh[MROWS * DDIM];
__device__ __half g_Kh[MROWS * DDIM];
__device__ __half g_Vh[MROWS * DDIM];
__device__ __half g_Ah[MROWS * DDIM];
__device__ __half g_Wqh[DDIM * DDIM];
__device__ __half g_Wkh[DDIM * DDIM];
__device__ __half g_Wvh[DDIM * DDIM], g_Wvl[DDIM * DDIM];
__device__ __half g_Woh[DDIM * DDIM], g_Wol[DDIM * DDIM];
__device__ float  g_O[MROWS * DDIM];

// ===========================================================================
// helpers
// ===========================================================================
__device__ __forceinline__ uint32_t smem_u32(const void* p) {
    uint32_t a;
    asm("{ .reg .u64 t; cvta.to.shared.u64 t, %1; cvt.u32.u64 %0, t; }"
        : "=r"(a) : "l"(p));
    return a;
}
__device__ __forceinline__ void ldmx4(uint32_t (&r)[4], uint32_t addr) {
    asm volatile("ldmatrix.sync.aligned.m8n8.x4.shared.b16 {%0,%1,%2,%3}, [%4];"
                 : "=r"(r[0]), "=r"(r[1]), "=r"(r[2]), "=r"(r[3]) : "r"(addr));
}
__device__ __forceinline__ void ldmx4t(uint32_t (&r)[4], uint32_t addr) {
    asm volatile("ldmatrix.sync.aligned.m8n8.x4.trans.shared.b16 {%0,%1,%2,%3}, [%4];"
                 : "=r"(r[0]), "=r"(r[1]), "=r"(r[2]), "=r"(r[3]) : "r"(addr));
}
__device__ __forceinline__ void mma16816(float (&c)[4], const uint32_t (&a)[4],
                                         const uint32_t (&b)[2]) {
    asm volatile(
        "mma.sync.aligned.m16n8k16.row.col.f32.f16.f16.f32 "
        "{%0,%1,%2,%3}, {%4,%5,%6,%7}, {%8,%9}, {%0,%1,%2,%3};"
        : "+f"(c[0]), "+f"(c[1]), "+f"(c[2]), "+f"(c[3])
        : "r"(a[0]), "r"(a[1]), "r"(a[2]), "r"(a[3]), "r"(b[0]), "r"(b[1]));
}
__device__ __forceinline__ uint32_t packf16(float x0, float x1) {
    uint32_t r;
    asm("cvt.rn.f16x2.f32 %0, %1, %2;" : "=r"(r) : "f"(x1), "f"(x0));
    return r;
}
__device__ __forceinline__ uint32_t h2exp2i(uint32_t x) {
    uint32_t r;
    asm("ex2.approx.f16x2 %0, %1;" : "=r"(r) : "r"(x));
    return r;
}
__device__ __forceinline__ uint32_t hadd2i(uint32_t a, uint32_t b) {
    uint32_t r;
    asm("add.f16x2 %0, %1, %2;" : "=r"(r) : "r"(a), "r"(b));
    return r;
}
__device__ __forceinline__ void cp16(uint32_t dst, const void* src) {
    asm volatile("cp.async.cg.shared.global [%0], [%1], 16;"
                 :: "r"(dst), "l"(src) : "memory");
}
#define CP_COMMIT() asm volatile("cp.async.commit_group;" ::: "memory")
#define CP_WAIT(n)  asm volatile("cp.async.wait_group %0;" :: "n"(n) : "memory")

// XOR chunk swizzle for 32-half (64B) rows: conflict-free fills + ldmatrix
__device__ __forceinline__ int swz(int r, int c) {   // half offset in tile
    return r * 32 + ((c ^ ((r >> 1) & 3)) << 3);
}

// ===========================================================================
// fused prep: x -> Xh (blocks 0..16383); weights (blocks 16384..17407):
//   z=0: Wq -> hi; z=1: Wk -> hi; z=2: Wv -> hi+lo; z=3: Wo -> hi+lo.
// ===========================================================================
__global__ __launch_bounds__(256) void prep_kernel(
    const float* __restrict__ x,
    const float* __restrict__ Wq, const float* __restrict__ Wk,
    const float* __restrict__ Wv, const float* __restrict__ Wo,
    __half* __restrict__ Xh,
    __half* __restrict__ Wqh, __half* __restrict__ Wkh,
    __half* __restrict__ Wvh, __half* __restrict__ Wvl,
    __half* __restrict__ Woh, __half* __restrict__ Wol)
{
    const int b = blockIdx.x;
    if (b < 16384) {
        int i = b * 256 + threadIdx.x;
        Xh[i] = __float2half_rn(x[i]);
    } else {
        int zb = b - 16384;
        int z  = zb >> 8;
        int i  = (zb & 255) * 256 + threadIdx.x;
        if (z == 0) {
            Wqh[i] = __float2half_rn(Wq[i]);
        } else if (z == 1) {
            Wkh[i] = __float2half_rn(Wk[i]);
        } else if (z == 2) {
            float v = Wv[i];
            __half h = __float2half_rn(v);
            Wvh[i] = h;
            Wvl[i] = __float2half_rn(v - __half2float(h));
        } else {
            float v = Wo[i];
            __half h = __float2half_rn(v);
            Woh[i] = h;
            Wol[i] = __float2half_rn(v - __half2float(h));
        }
    }
}

// ===========================================================================
// Persistent weights-resident GEMM: CTA = 64n column stripe; W tile loaded
// ONCE; CTA iterates over `nblocks` 128-row M-blocks with A (hi plane only)
// streamed in a 3-STAGE ring of 32-col chunks.  8 warps (4m x 2n).
// RACE-SAFE BY CONSTRUCTION: with the barrier placed before compute, maximum
// warp skew lets the leader prefetch stage gs+2 while the laggard still reads
// stage gs; buffers (gs+2)%3 != gs%3 always, so no trailing barrier needed.
// nterms: 1 -> Ah*Wh;  2 -> Ah*(Wh+Wl).   outmode: 0=f32, 2=hi.
// smem: WH 0..32K, WL 32..64K, X stage s at 64K + (s%3)*8K.  Total 88K.
// ===========================================================================
#define GEMM_SMEM 90112

__device__ __forceinline__ void gemm_body64(
    const __half* __restrict__ Aph,
    const __half* __restrict__ Wph, const __half* __restrict__ Wpl,
    const float* __restrict__ bias, float outscale, int outmode, int nterms,
    int nblocks,
    __half* __restrict__ Ch, float* __restrict__ Cf,
    int bm0, int bn, uint32_t sb)
{
    const int tid  = threadIdx.x;
    const int lane = tid & 31;
    const int wid  = tid >> 5;
    const int wm   = wid & 3;
    const int wn   = wid >> 2;
    const int qd   = lane >> 3;

    const uint32_t WH = sb;
    const uint32_t WL = sb + 32768;
    const uint32_t X0 = sb + 65536;

    // ---- prologue: W planes (one-time) + A stage 0 (ring slot 0)
    #pragma unroll
    for (int i = 0; i < 8; i++) {
        int s = tid + i * 256;            // 0..2047
        int r = s >> 5, cc = s & 31;      // row 0..63, col-chunk 0..31
        int kc = cc >> 2, c = cc & 3;
        uint32_t d = (uint32_t)(kc * 2048 + swz(r, c)) * 2;
        size_t src = (size_t)(bn + r) * 256 + cc * 8;
        cp16(WH + d, &Wph[src]);
        if (nterms >= 2) cp16(WL + d, &Wpl[src]);
    }
    #pragma unroll
    for (int i = 0; i < 2; i++) {
        int s = tid + i * 256;
        int r = s >> 2, c = s & 3;
        uint32_t d = (uint32_t)swz(r, c) * 2;
        size_t src = (size_t)(bm0 + r) * 256 + c * 8;
        cp16(X0 + d, &Aph[src]);
    }
    CP_COMMIT();

    const int a_row = wm * 32 + (lane & 15);
    const int b_row = wn * 32 + (qd & 1) * 8 + (lane & 7);
    const int nstages = nblocks * 8;

    int slot = 0;        // ring slot of the current stage (gs % 3)
    int nslot = 1;       // ring slot of the next stage

    #pragma unroll 1
    for (int it = 0; it < nblocks; it++) {
        const int bm = bm0 + it * 128;

        float acc[2][4][4];
        #pragma unroll
        for (int i = 0; i < 2; i++)
            #pragma unroll
            for (int j = 0; j < 4; j++)
                #pragma unroll
                for (int k = 0; k < 4; k++) acc[i][j][k] = 0.f;

        #pragma unroll 1
        for (int kc = 0; kc < 8; kc++) {
            const int gs = it * 8 + kc;
            if (gs + 1 < nstages) {
                const int ngs = gs + 1;
                const int nbm = bm0 + (ngs >> 3) * 128;
                const int nk0 = (ngs & 7) * 32;
                uint32_t xh = X0 + (uint32_t)nslot * 8192;
                #pragma unroll
                for (int i = 0; i < 2; i++) {
                    int s = tid + i * 256;
                    int r = s >> 2, c = s & 3;
                    uint32_t d = (uint32_t)swz(r, c) * 2;
                    size_t src = (size_t)(nbm + r) * 256 + nk0 + c * 8;
                    cp16(xh + d, &Aph[src]);
                }
                CP_COMMIT();
                CP_WAIT(1);
            } else {
                CP_WAIT(0);
            }
            __syncthreads();

            const uint32_t xh = X0 + (uint32_t)slot * 8192;
            const uint32_t wkc = (uint32_t)(kc * 2048) * 2;

            #pragma unroll
            for (int ks = 0; ks < 32; ks += 16) {
                uint32_t ah[2][4];
                #pragma unroll
                for (int mt = 0; mt < 2; mt++) {
                    int row = a_row + mt * 16;
                    int c   = (lane >> 4) + (ks >> 3);
                    uint32_t off = (uint32_t)swz(row, c) * 2;
                    ldmx4(ah[mt], xh + off);
                }
                uint32_t bh[4][2], bl[4][2];
                #pragma unroll
                for (int j = 0; j < 2; j++) {
                    int row = b_row + 16 * j;
                    int c   = (qd >> 1) + (ks >> 3);
                    uint32_t off = (uint32_t)swz(row, c) * 2;
                    uint32_t r4[4];
                    ldmx4(r4, WH + wkc + off);
                    bh[2*j][0] = r4[0]; bh[2*j+1][0] = r4[1];
                    bh[2*j][1] = r4[2]; bh[2*j+1][1] = r4[3];
                    if (nterms >= 2) {
                        ldmx4(r4, WL + wkc + off);
                        bl[2*j][0] = r4[0]; bl[2*j+1][0] = r4[1];
                        bl[2*j][1] = r4[2]; bl[2*j+1][1] = r4[3];
                    }
                }
                #pragma unroll
                for (int mt = 0; mt < 2; mt++)
                    #pragma unroll
                    for (int nt = 0; nt < 4; nt++) {
                        mma16816(acc[mt][nt], ah[mt], bh[nt]);
                        if (nterms >= 2) mma16816(acc[mt][nt], ah[mt], bl[nt]);
                    }
            }
            // advance ring (no trailing barrier needed with 3 slots)
            slot = nslot;
            nslot = (nslot == 2) ? 0 : nslot + 1;
        }

        // ---- epilogue for this block (regs + gmem only; no smem)
        #pragma unroll
        for (int mt = 0; mt < 2; mt++) {
            #pragma unroll
            for (int nt = 0; nt < 4; nt++) {
                int r0 = bm + wm * 32 + mt * 16 + (lane >> 2);
                int c  = bn + wn * 32 + nt * 8 + (lane & 3) * 2;
                float b0 = bias[c], b1 = bias[c + 1];
                float v00 = (acc[mt][nt][0] + b0) * outscale;
                float v01 = (acc[mt][nt][1] + b1) * outscale;
                float v10 = (acc[mt][nt][2] + b0) * outscale;
                float v11 = (acc[mt][nt][3] + b1) * outscale;
                if (outmode == 2) {
                    *reinterpret_cast<uint32_t*>(&Ch[(size_t)r0 * 256 + c]) =
                        packf16(v00, v01);
                    *reinterpret_cast<uint32_t*>(&Ch[(size_t)(r0 + 8) * 256 + c]) =
                        packf16(v10, v11);
                } else {
                    *reinterpret_cast<float2*>(&Cf[(size_t)r0 * 256 + c]) =
                        make_float2(v00, v01);
                    *reinterpret_cast<float2*>(&Cf[(size_t)(r0 + 8) * 256 + c]) =
                        make_float2(v10, v11);
                }
            }
        }
    }
}

// fused QKV projection: grid (4, 32, 3); 4 M-blocks per CTA (384 CTAs —
// all SMs busy at occ 2).  Q/K: 1-term.  V: 2-term (direct output path).
__global__ __launch_bounds__(256, 2) void gemm_qkv(
    const __half* __restrict__ Xh,
    const __half* __restrict__ Wqh, const __half* __restrict__ Wkh,
    const __half* __restrict__ Wvh, const __half* __restrict__ Wvl,
    const float* __restrict__ bq, const float* __restrict__ bk,
    const float* __restrict__ bv,
    __half* __restrict__ Qh, __half* __restrict__ Kh, __half* __restrict__ Vh,
    float qscale)
{
    extern __shared__ __align__(16) char gsm[];
    const int z = blockIdx.z;
    const __half* Wph = (z == 0) ? Wqh : (z == 1) ? Wkh : Wvh;
    const __half* Wpl = (z == 2) ? Wvl : nullptr;
    const float* bias = (z == 0) ? bq : (z == 1) ? bk : bv;
    __half* Ch = (z == 0) ? Qh : (z == 1) ? Kh : Vh;
    const float sc = (z == 0) ? qscale : 1.f;
    const int nterms = (z == 2) ? 2 : 1;

    gemm_body64(Xh, Wph, Wpl, bias, sc, 2, nterms, 4,
                Ch, nullptr,
                blockIdx.y * 512, blockIdx.x * 64, smem_u32(gsm));
}

// O projection (f32 out), grid (4, 64); 2 M-blocks per CTA; 2-term.
__global__ __launch_bounds__(256, 2) void gemm_o(
    const __half* __restrict__ Aph,
    const __half* __restrict__ Wph, const __half* __restrict__ Wpl,
    const float* __restrict__ bias, float* __restrict__ Cf)
{
    extern __shared__ __align__(16) char gsm[];
    gemm_body64(Aph, Wph, Wpl, bias, 1.f, 0, 2, 2, nullptr, Cf,
                blockIdx.y * 256, blockIdx.x * 64, smem_u32(gsm));
}

// ===========================================================================
// Flash attention via mma.sync (16 q-rows/warp, occ 3), 128-key smem tiles
// (2x64-key sub-rounds), cp.async double buffering (trailing sync: safe).
// FIXED-BIAS softmax p = exp2(s - 8) in f16x2; HADD2 row sums.
// QK^T = qh*kh.  PV: P,V single fp16.
// ===========================================================================
#define TILE_HALFS (128 * 32)
#define TILE_BYTES (TILE_HALFS * 2)   // 8192
#define SM_BIAS 8.0f

__global__ __launch_bounds__(256, 3) void attn_mma(
    const __half* __restrict__ Qh,
    const __half* __restrict__ Kh, const __half* __restrict__ Vh,
    __half* __restrict__ Aoh)
{
    __shared__ __align__(16) __half Ksh[2][TILE_HALFS];
    __shared__ __align__(16) __half Vsh[2][TILE_HALFS];

    const int tid  = threadIdx.x;
    const int lane = tid & 31;
    const int w    = tid >> 5;                  // 0..7
    const int qd   = lane >> 3;
    const int n    = blockIdx.z;
    const int h    = blockIdx.y;
    const int qbase = blockIdx.x * 128 + w * 16;
    const size_t seqoff = (size_t)n * LSEQ * 256 + h * 32;

    const uint32_t kh0 = smem_u32(&Ksh[0][0]);
    const uint32_t vh0 = smem_u32(&Vsh[0][0]);

    // prologue: prefetch tile 0 (128 keys) into buffer 0
    #pragma unroll
    for (int i = 0; i < 2; i++) {
        int s = tid + i * 256;
        int r = s >> 2, c = s & 3;
        uint32_t d = (uint32_t)swz(r, c) * 2;
        size_t src = seqoff + (size_t)r * 256 + c * 8;
        cp16(kh0 + d, &Kh[src]);
        cp16(vh0 + d, &Vh[src]);
    }
    CP_COMMIT();

    // Q fragments (overlap with prefetch)
    uint32_t qh[2][4];
    #pragma unroll
    for (int kt = 0; kt < 2; kt++)
        #pragma unroll
        for (int pi = 0; pi < 4; pi++) {
            int row = qbase + (lane >> 2) + ((pi & 1) ? 8 : 0);
            int col = kt * 16 + (lane & 3) * 2 + ((pi & 2) ? 8 : 0);
            qh[kt][pi] = *reinterpret_cast<const uint32_t*>(
                &Qh[seqoff + (size_t)row * 256 + col]);
        }

    float out[4][4];
    #pragma unroll
    for (int j = 0; j < 4; j++)
        #pragma unroll
        for (int k = 0; k < 4; k++) out[j][k] = 0.f;
    float lpart[2] = {0.f, 0.f};

    const int kb_rowc = (qd & 1) * 8 + (lane & 7);

    #pragma unroll 1
    for (int t = 0; t < 8; t++) {
        const int buf = t & 1;
        if (t + 1 < 8) {
            const uint32_t bo = (buf ^ 1) * TILE_BYTES;
            #pragma unroll
            for (int i = 0; i < 2; i++) {
                int s = tid + i * 256;
                int r = s >> 2, c = s & 3;
                uint32_t d = (uint32_t)swz(r, c) * 2;
                size_t src = seqoff + (size_t)((t + 1) * 128 + r) * 256 + c * 8;
                cp16(kh0 + bo + d, &Kh[src]);
                cp16(vh0 + bo + d, &Vh[src]);
            }
            CP_COMMIT();
            CP_WAIT(1);
        } else {
            CP_WAIT(0);
        }
        __syncthreads();

        const uint32_t khB = kh0 + buf * TILE_BYTES;
        const uint32_t vhB = vh0 + buf * TILE_BYTES;

        #pragma unroll
        for (int s64 = 0; s64 < 2; s64++) {
            const int rbase = s64 * 64;

            // ---- scores S[16 q, 64 k], accumulator pre-biased to -8
            float sc[8][4];
            #pragma unroll
            for (int j = 0; j < 8; j++)
                #pragma unroll
                for (int k = 0; k < 4; k++) sc[j][k] = -SM_BIAS;

            #pragma unroll
            for (int kt = 0; kt < 2; kt++) {
                uint32_t bh[8][2];
                #pragma unroll
                for (int j = 0; j < 4; j++) {
                    int row = rbase + kb_rowc + 16 * j;
                    int c   = kt * 2 + (qd >> 1);
                    uint32_t off = (uint32_t)swz(row, c) * 2;
                    uint32_t r4[4];
                    ldmx4(r4, khB + off);
                    bh[2*j][0] = r4[0]; bh[2*j+1][0] = r4[1];
                    bh[2*j][1] = r4[2]; bh[2*j+1][1] = r4[3];
                }
                #pragma unroll
                for (int nt = 0; nt < 8; nt++)
                    mma16816(sc[nt], qh[kt], bh[nt]);
            }

            // ---- pack + f16x2 exp2 (outputs ARE the PV fragments)
            uint32_t p16[8][2];
            #pragma unroll
            for (int nt = 0; nt < 8; nt++) {
                p16[nt][0] = h2exp2i(packf16(sc[nt][0], sc[nt][1]));
                p16[nt][1] = h2exp2i(packf16(sc[nt][2], sc[nt][3]));
            }

            // ---- row-sum trees (HADD2), accumulate lsum in f32
            #pragma unroll
            for (int s = 0; s < 2; s++) {
                uint32_t t01 = hadd2i(p16[0][s], p16[1][s]);
                uint32_t t23 = hadd2i(p16[2][s], p16[3][s]);
                uint32_t t45 = hadd2i(p16[4][s], p16[5][s]);
                uint32_t t67 = hadd2i(p16[6][s], p16[7][s]);
                uint32_t tt  = hadd2i(hadd2i(t01, t23), hadd2i(t45, t67));
                __half2 hh = *reinterpret_cast<__half2*>(&tt);
                float2 ff = __half22float2(hh);
                lpart[s] += ff.x + ff.y;
            }

            // ---- PV: out += P @ V
            #pragma unroll
            for (int ktpv = 0; ktpv < 4; ktpv++) {
                uint32_t pah[4];
                pah[0] = p16[2 * ktpv][0];
                pah[1] = p16[2 * ktpv][1];
                pah[2] = p16[2 * ktpv + 1][0];
                pah[3] = p16[2 * ktpv + 1][1];

                uint32_t vh[4][2];
                #pragma unroll
                for (int j = 0; j < 2; j++) {
                    int row = rbase + ktpv * 16 + kb_rowc;
                    int c   = 2 * j + (qd >> 1);
                    uint32_t off = (uint32_t)swz(row, c) * 2;
                    uint32_t r4[4];
                    ldmx4t(r4, vhB + off);
                    vh[2*j][0] = r4[0];   vh[2*j][1] = r4[1];
                    vh[2*j+1][0] = r4[2]; vh[2*j+1][1] = r4[3];
                }
                #pragma unroll
                for (int ntd = 0; ntd < 4; ntd++)
                    mma16816(out[ntd], pah, vh[ntd]);
            }
        }
        __syncthreads();
    }

    // ---- finalize
    float inv[2];
    #pragma unroll
    for (int s = 0; s < 2; s++) {
        float ls = lpart[s];
        ls += __shfl_xor_sync(0xffffffffu, ls, 1);
        ls += __shfl_xor_sync(0xffffffffu, ls, 2);
        inv[s] = 1.f / ls;
    }
    #pragma unroll
    for (int ntd = 0; ntd < 4; ntd++) {
        int r0 = qbase + (lane >> 2);
        int c  = h * 32 + ntd * 8 + (lane & 3) * 2;
        size_t base = (size_t)n * LSEQ * 256;
        float v00 = out[ntd][0] * inv[0];
        float v01 = out[ntd][1] * inv[0];
        float v10 = out[ntd][2] * inv[1];
        float v11 = out[ntd][3] * inv[1];
        *reinterpret_cast<uint32_t*>(&Aoh[base + (size_t)r0 * 256 + c]) =
            packf16(v00, v01);
        *reinterpret_cast<uint32_t*>(&Aoh[base + (size_t)(r0 + 8) * 256 + c]) =
            packf16(v10, v11);
    }
}

// ---------------------------------------------------------------------------
// Softmax pooling over L per (n, d)
// ---------------------------------------------------------------------------
__global__ __launch_bounds__(256) void pool_kernel(
    const float* __restrict__ O, float* __restrict__ out)
{
    const int n  = blockIdx.y;
    const int d0 = blockIdx.x * 32;
    const int dc = threadIdx.x & 31;
    const int g  = threadIdx.x >> 5;
    const int d  = d0 + dc;

    float m = -INFINITY, se = 0.f, sex = 0.f;
    for (int l = g; l < LSEQ; l += 8) {
        float x = O[((size_t)n * LSEQ + l) * DDIM + d];
        if (x > m) {
            float c = __expf(m - x);
            se *= c; sex *= c; m = x;
        }
        float p = __expf(x - m);
        se += p; sex += p * x;
    }

    __shared__ float sm[8][32], sse[8][32], ssex[8][32];
    sm[g][dc] = m; sse[g][dc] = se; ssex[g][dc] = sex;
    __syncthreads();

    if (g == 0) {
        #pragma unroll
        for (int o = 1; o < 8; o++) {
            float m2 = sm[o][dc], se2 = sse[o][dc], sex2 = ssex[o][dc];
            if (m2 > m) {
                float c = __expf(m - m2);
                se *= c; sex *= c; m = m2;
            }
            float c2 = __expf(m2 - m);
            se += se2 * c2; sex += sex2 * c2;
        }
        out[(size_t)n * DDIM + d] = sex / se;
    }
}

// ---------------------------------------------------------------------------
// Launch
// ---------------------------------------------------------------------------
extern "C" void kernel_launch(void* const* d_in, const int* in_sizes, int n_in,
                              void* d_out, int out_size)
{
    const float* x  = (const float*)d_in[0];
    const float* Wq = (const float*)d_in[1];
    const float* bq = (const float*)d_in[2];
    const float* Wk = (const float*)d_in[3];
    const float* bk = (const float*)d_in[4];
    const float* Wv = (const float*)d_in[5];
    const float* bv = (const float*)d_in[6];
    const float* Wo = (const float*)d_in[7];
    const float* bo = (const float*)d_in[8];
    float* out = (float*)d_out;

    __half *Xh, *Qh, *Kh, *Vh, *Ah;
    __half *Wqh, *Wkh, *Wvh, *Wvl, *Woh, *Wol;
    float* O;
    cudaGetSymbolAddress((void**)&Xh, g_Xh);
    cudaGetSymbolAddress((void**)&Qh, g_Qh);
    cudaGetSymbolAddress((void**)&Kh, g_Kh);
    cudaGetSymbolAddress((void**)&Vh, g_Vh);
    cudaGetSymbolAddress((void**)&Ah, g_Ah);
    cudaGetSymbolAddress((void**)&Wqh, g_Wqh);
    cudaGetSymbolAddress((void**)&Wkh, g_Wkh);
    cudaGetSymbolAddress((void**)&Wvh, g_Wvh); cudaGetSymbolAddress((void**)&Wvl, g_Wvl);
    cudaGetSymbolAddress((void**)&Woh, g_Woh); cudaGetSymbolAddress((void**)&Wol, g_Wol);
    cudaGetSymbolAddress((void**)&O, g_O);

    cudaFuncSetAttribute(gemm_qkv, cudaFuncAttributeMaxDynamicSharedMemorySize,
                         GEMM_SMEM);
    cudaFuncSetAttribute(gemm_o, cudaFuncAttributeMaxDynamicSharedMemorySize,
                         GEMM_SMEM);

    // exp2-domain scale: (1/sqrt(DH)) * log2(e)
    const float qscale = 0.17677669529663687f * 1.4426950408889634f;

    prep_kernel<<<16384 + 4 * 256, 256>>>(x, Wq, Wk, Wv, Wo,
                                          Xh, Wqh, Wkh, Wvh, Wvl, Woh, Wol);

    dim3 qkvGrid(4, 32, 3);     // 384 CTAs — full chip at occ 2
    gemm_qkv<<<qkvGrid, 256, GEMM_SMEM>>>(Xh, Wqh, Wkh, Wvh, Wvl,
                                          bq, bk, bv, Qh, Kh, Vh, qscale);

    dim3 aGrid(LSEQ / 128, NHEAD, NSEQ);   // (8, 8, 16) = 1024 CTAs
    attn_mma<<<aGrid, 256>>>(Qh, Kh, Vh, Ah);

    dim3 oGrid(4, 64);          // 2 M-blocks per CTA
    gemm_o<<<oGrid, 256, GEMM_SMEM>>>(Ah, Woh, Wol, bo, O);

    dim3 pGrid(DDIM / 32, NSEQ);
    pool_kernel<<<pGrid, 256>>>(O, out);
}